// round 6
// baseline (speedup 1.0000x reference)
#include <cuda_runtime.h>
#include <math.h>

#define BB 64        // batch
#define TT 512       // seq len
#define HH 256       // hidden
#define G4 1024      // 4*H
#define NCLS 20

#define CLU 8        // cluster size (CTAs per bgrp)
#define NBGRP 16     // batch groups (4 batches each)

// Scratch (static device globals — no runtime allocation)
__device__ float g_xz[(size_t)BB * TT * G4];   // 128 MB
__device__ float g_hfin[BB * HH];              // final h_T

// ---------------------------------------------------------------------------
// helpers
// ---------------------------------------------------------------------------
__device__ __forceinline__ unsigned long long ffma2(unsigned long long a,
                                                    unsigned long long b,
                                                    unsigned long long c) {
    unsigned long long d;
    asm("fma.rn.f32x2 %0, %1, %2, %3;" : "=l"(d) : "l"(a), "l"(b), "l"(c));
    return d;
}
__device__ __forceinline__ float sum2(unsigned long long v) {
    float lo, hi;
    asm("mov.b64 {%0, %1}, %2;" : "=f"(lo), "=f"(hi) : "l"(v));
    return lo + hi;
}
__device__ __forceinline__ float tanh_ap(float x) {
    float y;
    asm("tanh.approx.f32 %0, %1;" : "=f"(y) : "f"(x));
    return y;
}
__device__ __forceinline__ float sigm_ap(float x) {
    return fmaf(0.5f, tanh_ap(0.5f * x), 0.5f);
}
__device__ __forceinline__ unsigned my_ctarank() {
    unsigned r;
    asm("mov.u32 %0, %%cluster_ctarank;" : "=r"(r));
    return r;
}
__device__ __forceinline__ void st_dsmem_f32(unsigned local_addr, int rank, float v) {
    unsigned rem;
    asm volatile("mapa.shared::cluster.u32 %0, %1, %2;"
                 : "=r"(rem) : "r"(local_addr), "r"(rank));
    asm volatile("st.shared::cluster.f32 [%0], %1;" :: "r"(rem), "f"(v));
}

// ---------------------------------------------------------------------------
// Phase A: xz[b,t,:] = emb[x[b,t]] @ W + bias      (M=32768, K=256, N=1024)
// 128x128 tile, 256 threads, 8x8 micro-tile.   (unchanged)
// ---------------------------------------------------------------------------
__global__ __launch_bounds__(256) void phaseA_kernel(
    const int* __restrict__ x, const float* __restrict__ emb,
    const float* __restrict__ W, const float* __restrict__ bias)
{
    __shared__ float As[16][136];
    __shared__ float Bs[16][136];
    __shared__ int ridx[128];

    const int tid = threadIdx.x;
    const int bx = blockIdx.x;   // 0..7
    const int by = blockIdx.y;   // 0..255

    if (tid < 128) ridx[tid] = x[by * 128 + tid];
    __syncthreads();

    const int tx = tid & 15;
    const int ty = tid >> 4;

    float acc[8][8];
#pragma unroll
    for (int i = 0; i < 8; i++)
#pragma unroll
        for (int j = 0; j < 8; j++) acc[i][j] = 0.f;

    const int ar  = tid >> 1;
    const int akq = (tid & 1) << 3;
    const int bkk = tid >> 4;
    const int bc8 = (tid & 15) << 3;

    for (int k0 = 0; k0 < 256; k0 += 16) {
        {
            const float* ap = emb + (size_t)ridx[ar] * 256 + k0 + akq;
            float4 va = *(const float4*)(ap);
            float4 vb = *(const float4*)(ap + 4);
            As[akq + 0][ar] = va.x; As[akq + 1][ar] = va.y;
            As[akq + 2][ar] = va.z; As[akq + 3][ar] = va.w;
            As[akq + 4][ar] = vb.x; As[akq + 5][ar] = vb.y;
            As[akq + 6][ar] = vb.z; As[akq + 7][ar] = vb.w;
            const float* bp = W + (size_t)(k0 + bkk) * G4 + bx * 128 + bc8;
            *(float4*)&Bs[bkk][bc8]     = *(const float4*)(bp);
            *(float4*)&Bs[bkk][bc8 + 4] = *(const float4*)(bp + 4);
        }
        __syncthreads();
#pragma unroll
        for (int k = 0; k < 16; k++) {
            float a[8], b[8];
            float4 a0 = *(const float4*)&As[k][ty << 3];
            float4 a1 = *(const float4*)&As[k][(ty << 3) + 4];
            float4 b0 = *(const float4*)&Bs[k][tx << 3];
            float4 b1 = *(const float4*)&Bs[k][(tx << 3) + 4];
            a[0]=a0.x; a[1]=a0.y; a[2]=a0.z; a[3]=a0.w;
            a[4]=a1.x; a[5]=a1.y; a[6]=a1.z; a[7]=a1.w;
            b[0]=b0.x; b[1]=b0.y; b[2]=b0.z; b[3]=b0.w;
            b[4]=b1.x; b[5]=b1.y; b[6]=b1.z; b[7]=b1.w;
#pragma unroll
            for (int i = 0; i < 8; i++)
#pragma unroll
                for (int j = 0; j < 8; j++)
                    acc[i][j] = fmaf(a[i], b[j], acc[i][j]);
        }
        __syncthreads();
    }

    const int colbase = bx * 128 + (tx << 3);
    float4 bv0 = *(const float4*)(bias + colbase);
    float4 bv1 = *(const float4*)(bias + colbase + 4);
#pragma unroll
    for (int i = 0; i < 8; i++) {
        int row = by * 128 + (ty << 3) + i;
        float4 o0 = make_float4(acc[i][0] + bv0.x, acc[i][1] + bv0.y,
                                acc[i][2] + bv0.z, acc[i][3] + bv0.w);
        float4 o1 = make_float4(acc[i][4] + bv1.x, acc[i][5] + bv1.y,
                                acc[i][6] + bv1.z, acc[i][7] + bv1.w);
        float* op = g_xz + (size_t)row * G4 + colbase;
        *(float4*)(op)     = o0;
        *(float4*)(op + 4) = o1;
    }
}

// ---------------------------------------------------------------------------
// Phase B: 512 LSTM steps. Grid = 128 CTAs = 16 bgrps x 8-CTA clusters.
// Cluster CTA (rank jgrp) owns 4 batches x 32 hidden cols; U slice (128 gate
// cols x 256 k = 128 KB) resident in smem. h exchange: gate threads PUSH their
// h value into all 8 cluster CTAs' double-buffered h stage via st.shared::cluster;
// one barrier.cluster per step (release/acquire covers the DSMEM stores).
// 512 threads: quarter q accumulates k in [q*64, q*64+64) with FFMA2.
// ---------------------------------------------------------------------------
#define UTS 260                      // row stride (floats)
#define UT_FLOATS (128 * UTS)        // 33280
#define HSBUF (4 * UTS)              // one h-stage buffer: 4 rows
#define HS_OFF UT_FLOATS
#define PART_OFF (HS_OFF + 2 * HSBUF)
#define SMEM_B ((PART_OFF + 3 * 128 * 4) * 4)

extern __shared__ float sdyn[];

__global__ __launch_bounds__(512, 1) __cluster_dims__(CLU, 1, 1)
void phaseB_kernel(const float* __restrict__ U)
{
    float* Ut   = sdyn;                  // [128][260]
    float* hs   = sdyn + HS_OFF;         // [2][4][260]
    float* part = sdyn + PART_OFF;       // [3][128][4]

    const int tid  = threadIdx.x;        // 512
    const int jgrp = (int)my_ctarank();  // 0..7  (cluster rank)
    const int bgrp = blockIdx.x >> 3;    // 0..15

    // Stage U slice: gcol = g*32+jj  ->  global col g*256 + jgrp*32 + jj
    for (int i = tid; i < 128 * 256; i += 512) {
        int k = i >> 7, gcol = i & 127;
        int g = gcol >> 5, jj = gcol & 31;
        Ut[gcol * UTS + k] = U[(size_t)k * G4 + g * HH + jgrp * 32 + jj];
    }
    // zero both h stages (h_0 = 0)
    for (int i = tid; i < 2 * HSBUF; i += 512) hs[i] = 0.f;

    const int quarter = tid >> 7;        // 0..3
    const int cell    = tid & 127;
    const int jj      = cell >> 2;       // 0..31
    const int bl      = cell & 3;        // 0..3
    const int b       = bgrp * 4 + bl;
    const int j       = jgrp * 32 + jj;  // hidden col
    const int kb      = quarter << 6;

    float c = 0.f;
    const float* xzp = g_xz + (size_t)b * TT * G4 + j;

    const ulonglong2* u0 = (const ulonglong2*)(Ut + (0 * 32 + jj) * UTS + kb);
    const ulonglong2* u1 = (const ulonglong2*)(Ut + (1 * 32 + jj) * UTS + kb);
    const ulonglong2* u2 = (const ulonglong2*)(Ut + (2 * 32 + jj) * UTS + kb);
    const ulonglong2* u3 = (const ulonglong2*)(Ut + (3 * 32 + jj) * UTS + kb);

    const unsigned smem_base = (unsigned)__cvta_generic_to_shared(sdyn);
    // push target offset (bytes) within each peer's smem, minus buffer select
    const unsigned push_off = smem_base + 4u * (HS_OFF + (unsigned)(bl * UTS + j));

    // all 8 CTAs' staging done before step 0
    asm volatile("barrier.cluster.arrive.aligned;" ::: "memory");
    asm volatile("barrier.cluster.wait.aligned;" ::: "memory");

    for (int t = 0; t < TT; t++) {
        // xz prefetch (quarter 0 only; independent of compute)
        float a0 = 0.f, a1 = 0.f, a2 = 0.f, a3 = 0.f;
        if (quarter == 0) {
            const float* xr = xzp + (size_t)t * G4;
            a0 = __ldg(xr + 0 * HH);
            a1 = __ldg(xr + 1 * HH);
            a2 = __ldg(xr + 2 * HH);
            a3 = __ldg(xr + 3 * HH);
        }

        const ulonglong2* hrow =
            (const ulonglong2*)(hs + (t & 1) * HSBUF + bl * UTS + kb);

        unsigned long long s0 = 0ull, s1 = 0ull, s2 = 0ull, s3 = 0ull;
#pragma unroll 4
        for (int k4 = 0; k4 < 16; k4++) {
            ulonglong2 hv = hrow[k4];
            ulonglong2 v0 = u0[k4];
            ulonglong2 v1 = u1[k4];
            ulonglong2 v2 = u2[k4];
            ulonglong2 v3 = u3[k4];
            s0 = ffma2(hv.x, v0.x, s0); s0 = ffma2(hv.y, v0.y, s0);
            s1 = ffma2(hv.x, v1.x, s1); s1 = ffma2(hv.y, v1.y, s1);
            s2 = ffma2(hv.x, v2.x, s2); s2 = ffma2(hv.y, v2.y, s2);
            s3 = ffma2(hv.x, v3.x, s3); s3 = ffma2(hv.y, v3.y, s3);
        }
        float p0 = sum2(s0), p1 = sum2(s1), p2 = sum2(s2), p3 = sum2(s3);

        if (quarter != 0) {
            *(float4*)&part[((quarter - 1) * 128 + cell) * 4] =
                make_float4(p0, p1, p2, p3);
            asm volatile("bar.arrive 2, 512;" ::: "memory");
        } else {
            asm volatile("bar.sync 2, 512;" ::: "memory");
            float4 q1 = *(const float4*)&part[(0 * 128 + cell) * 4];
            float4 q2 = *(const float4*)&part[(1 * 128 + cell) * 4];
            float4 q3 = *(const float4*)&part[(2 * 128 + cell) * 4];
            float z0 = a0 + p0 + q1.x + q2.x + q3.x;
            float z1 = a1 + p1 + q1.y + q2.y + q3.y;
            float z2 = a2 + p2 + q1.z + q2.z + q3.z;
            float z3 = a3 + p3 + q1.w + q2.w + q3.w;
            // gates (order i, f, g, o)
            float ig = sigm_ap(z0);
            float fg = sigm_ap(z1);
            float gg = tanh_ap(z2);
            float og = sigm_ap(z3);
            c = fmaf(fg, c, ig * gg);
            float hn = og * tanh_ap(c);
            // push h_{t+1}(b, j) into all 8 cluster CTAs' next h stage
            unsigned addr = push_off + 4u * (unsigned)(((t + 1) & 1) * HSBUF);
#pragma unroll
            for (int r = 0; r < CLU; r++) st_dsmem_f32(addr, r, hn);
            if (t == TT - 1) g_hfin[b * HH + j] = hn;
        }

        // cluster barrier: arrive(release: DSMEM pushes visible) + wait(acquire)
        asm volatile("barrier.cluster.arrive.aligned;" ::: "memory");
        asm volatile("barrier.cluster.wait.aligned;" ::: "memory");
    }
}

// ---------------------------------------------------------------------------
// Phase C: logits = h_T @ Wd + bd; softmax. One warp per batch row.
// ---------------------------------------------------------------------------
__global__ __launch_bounds__(32) void phaseC_kernel(
    const float* __restrict__ Wd, const float* __restrict__ bd,
    float* __restrict__ out)
{
    const int b = blockIdx.x;
    const int lane = threadIdx.x;
    const float* h = g_hfin + b * HH;

    float v = 0.f;
    if (lane < NCLS) {
#pragma unroll 8
        for (int k = 0; k < HH; k++)
            v = fmaf(h[k], Wd[k * NCLS + lane], v);
        v += bd[lane];
    }
    float m = (lane < NCLS) ? v : -1e30f;
#pragma unroll
    for (int o = 16; o; o >>= 1) m = fmaxf(m, __shfl_xor_sync(0xffffffffu, m, o));
    float e = (lane < NCLS) ? __expf(v - m) : 0.f;
    float s = e;
#pragma unroll
    for (int o = 16; o; o >>= 1) s += __shfl_xor_sync(0xffffffffu, s, o);
    if (lane < NCLS) out[b * NCLS + lane] = e / s;
}

// ---------------------------------------------------------------------------
extern "C" void kernel_launch(void* const* d_in, const int* in_sizes, int n_in,
                              void* d_out, int out_size)
{
    const int*   x    = (const int*)d_in[0];
    const float* emb  = (const float*)d_in[1];
    const float* W    = (const float*)d_in[2];
    const float* U    = (const float*)d_in[3];
    const float* bias = (const float*)d_in[4];
    const float* Wd   = (const float*)d_in[5];
    const float* bd   = (const float*)d_in[6];
    float* out = (float*)d_out;

    static bool inited = false;
    if (!inited) {
        cudaFuncSetAttribute(phaseB_kernel,
                             cudaFuncAttributeMaxDynamicSharedMemorySize, SMEM_B);
        inited = true;
    }

    phaseA_kernel<<<dim3(8, 256), 256>>>(x, emb, W, bias);
    phaseB_kernel<<<NBGRP * CLU, 512, SMEM_B>>>(U);
    phaseC_kernel<<<BB, 32>>>(Wd, bd, out);
}